// round 10
// baseline (speedup 1.0000x reference)
#include <cuda_runtime.h>

// 2-level 3D inverse db4 DWT.
// Kernel A: fused x+y synthesis per z-slice; band rows staged through smem in
//           8-row chunks (coalesced float2 gmem loads, zero redundancy), then
//           4-tap windows read from smem. Stage y float2-vectorized.
// Kernel B: streaming z synthesis, float2 per thread, z-segmented (R7 config).
// out[i] = sum_d lo[(i>>1)+d]*CLO[i&1][d] + hi[(i>>1)+d]*CHI[i&1][d]

#define BC 16  // batch * channels

// db4: CLO[p][d] = g0[6+p-2d], CHI[p][d] = g1[6+p-2d]; literals -> FFMA-imm
#define CLO00  0.032883011666982945f
#define CLO01 -0.18703481171888114f
#define CLO02  0.6308807679295904f
#define CLO03  0.23037781330885523f
#define CLO10 -0.010597401784997278f
#define CLO11  0.030841381835986965f
#define CLO12 -0.02798376941698385f
#define CLO13  0.7148465705525415f
#define CHI00  0.7148465705525415f
#define CHI01 -0.02798376941698385f
#define CHI02  0.030841381835986965f
#define CHI03 -0.010597401784997278f
#define CHI10 -0.23037781330885523f
#define CHI11 -0.6308807679295904f
#define CHI12  0.18703481171888114f
#define CHI13 -0.032883011666982945f

#define SYNTH(l0,l1,l2,l3,h0,h1,h2,h3,o0,o1)                              \
    do {                                                                  \
        o0 = l0*CLO00 + l1*CLO01 + l2*CLO02 + l3*CLO03                    \
           + h0*CHI00 + h1*CHI01 + h2*CHI02 + h3*CHI03;                   \
        o1 = l0*CLO10 + l1*CLO11 + l2*CLO12 + l3*CLO13                    \
           + h0*CHI10 + h1*CHI11 + h2*CHI12 + h3*CHI13;                   \
    } while (0)

// Scratch: xy-fused output [2][BC][Nz][M][M] (sized for level 0), + level-1 LL
__device__ float g_U[2ull * BC * 66 * 126 * 126];
__device__ float g_LL[(size_t)BC * 66 * 66 * 66];

// ---------------- Kernel A: fused x+y synthesis for one z-slice ----------------
// grid = (Nz, 2 trees, BC), 512 threads.
// smem: t[2][N][MP] (x-synth results) + sIn[4][8][N] (band-row staging chunk).
template<int N, bool LOW_LL>
__global__ __launch_bounds__(512)
void k_xy(const float* __restrict__ low_in, const float* __restrict__ highs) {
    constexpr int M   = 2 * N - 6;
    constexpr int MP  = M + 2;       // even -> aligned float2 smem rows
    constexpr int P   = N - 3;       // output pairs per axis
    constexpr int CHR = 8;           // staged rows per chunk
    constexpr int N2  = N / 2;       // float2 per band row (N even)
    extern __shared__ float sm[];
    float* t   = sm;                 // 2*N*MP floats
    float* sIn = sm + 2 * N * MP;    // 4*CHR*N floats

    const float* low = LOW_LL ? g_LL : low_in;
    const int z = blockIdx.x, i = blockIdx.y, b = blockIdx.z;
    const int tid = threadIdx.x;
    const size_t V  = (size_t)N * N * N;
    const size_t zb = (size_t)z * N * N;

    const int gl0 = 4 * i;
    const float* band0 = (gl0 == 0) ? (low + (size_t)b * V)
                                    : (highs + ((size_t)b * 7 + (gl0 - 1)) * V);
    const float* band1 = highs + ((size_t)b * 7 + gl0) * V;
    const float* band2 = highs + ((size_t)b * 7 + (4 * i + 1)) * V;
    const float* band3 = highs + ((size_t)b * 7 + (4 * i + 2)) * V;

    const int px = tid & 63;
    const int y0 = tid >> 6;         // 0..7

    // ---- stage x, chunked through smem ----
    for (int c = 0; c < N; c += CHR) {
        const int rows = (N - c < CHR) ? (N - c) : CHR;
        // coalesced float2 load of 4 bands x rows x N floats (no redundancy)
        const int tot2 = 4 * rows * N2;
        for (int s = tid; s < tot2; s += 512) {
            int x2   = s % N2;
            int rr   = (s / N2) % rows;
            int band = s / (N2 * rows);
            const float* src = (band == 0) ? band0 : (band == 1) ? band1
                              : (band == 2) ? band2 : band3;
            ((float2*)sIn)[(band * CHR + rr) * N2 + x2] =
                ((const float2*)(src + zb + (size_t)(c + rr) * N))[x2];
        }
        __syncthreads();
        // compute x-synthesis for this chunk from smem
        if (px < P && c + y0 < N) {
            const int y = c + y0;
            const float* r0 = &sIn[(0 * CHR + y0) * N + px];
            const float* r1 = &sIn[(1 * CHR + y0) * N + px];
            const float* r2 = &sIn[(2 * CHR + y0) * N + px];
            const float* r3 = &sIn[(3 * CHR + y0) * N + px];
            float a0 = r0[0], a1 = r0[1], a2 = r0[2], a3 = r0[3];
            float c0 = r1[0], c1 = r1[1], c2 = r1[2], c3 = r1[3];
            float e0 = r2[0], e1 = r2[1], e2 = r2[2], e3 = r2[3];
            float f0 = r3[0], f1 = r3[1], f2 = r3[2], f3 = r3[3];
            float o0, o1, p0, p1;
            SYNTH(a0, a1, a2, a3, c0, c1, c2, c3, o0, o1);
            SYNTH(e0, e1, e2, e3, f0, f1, f2, f3, p0, p1);
            *(float2*)&t[y * MP + 2 * px]       = make_float2(o0, o1);
            *(float2*)&t[(N + y) * MP + 2 * px] = make_float2(p0, p1);
        }
        __syncthreads();
    }

    // ---- stage y: float2 per thread along x; write g_U[i][b][z][*][*] ----
    {
        const int x2  = tid & 63;       // float2 index
        const int x   = 2 * x2;
        const int py0 = tid >> 6;       // 0..7
        if (x < M) {
            float* ub = g_U + ((((size_t)i * BC + b) * N + z) * M) * M + x;
            for (int py = py0; py < P; py += 8) {
                const float* r0 = &t[py * MP + x];        // sub-tree lo rows
                const float* r1 = &t[(N + py) * MP + x];  // sub-tree hi rows
                float2 l0 = *(const float2*)&r0[0];
                float2 l1 = *(const float2*)&r0[MP];
                float2 l2 = *(const float2*)&r0[2 * MP];
                float2 l3 = *(const float2*)&r0[3 * MP];
                float2 h0 = *(const float2*)&r1[0];
                float2 h1 = *(const float2*)&r1[MP];
                float2 h2 = *(const float2*)&r1[2 * MP];
                float2 h3 = *(const float2*)&r1[3 * MP];
                float2 o0, o1;
                SYNTH(l0.x, l1.x, l2.x, l3.x, h0.x, h1.x, h2.x, h3.x, o0.x, o1.x);
                SYNTH(l0.y, l1.y, l2.y, l3.y, h0.y, h1.y, h2.y, h3.y, o0.y, o1.y);
                float* d = ub + (size_t)(2 * py) * M;
                *(float2*)&d[0] = o0;
                *(float2*)&d[M] = o1;
            }
        }
    }
}

// ---------------- Kernel B: streaming z synthesis, float2, z-segmented ----------------
// (R7 configuration: measured 42.4us / 66.7% DRAM for level 0)
template<int NZ, int SEG, bool TO_LL>
__global__ __launch_bounds__(256)
void k_z(float* __restrict__ out_in, int plane2) {   // plane2 = plane/2
    const int pix = blockIdx.x * 256 + threadIdx.x;
    if (pix >= plane2) return;
    const int seg = blockIdx.y;
    const int b   = blockIdx.z;
    constexpr int MZ = 2 * NZ - 6;
    constexpr int P  = NZ - 3;
    constexpr int CH = (P + SEG - 1) / SEG;

    const int p0 = seg * CH;
    const int p1 = (p0 + CH < P) ? (p0 + CH) : P;

    float* out = TO_LL ? g_LL : out_in;
    const float2* lo = (const float2*)g_U + (size_t)b * NZ * plane2 + pix;
    const float2* hi = (const float2*)g_U + ((size_t)BC + b) * (size_t)NZ * plane2 + pix;
    float2* ob = (float2*)out + (size_t)b * MZ * plane2 + pix;

    float2 l0 = lo[(size_t)p0 * plane2];
    float2 l1 = lo[(size_t)(p0 + 1) * plane2];
    float2 l2 = lo[(size_t)(p0 + 2) * plane2];
    float2 h0 = hi[(size_t)p0 * plane2];
    float2 h1 = hi[(size_t)(p0 + 1) * plane2];
    float2 h2 = hi[(size_t)(p0 + 2) * plane2];
#pragma unroll 4
    for (int bz = p0; bz < p1; ++bz) {
        float2 l3 = lo[(size_t)(bz + 3) * plane2];
        float2 h3 = hi[(size_t)(bz + 3) * plane2];
        float2 o0, o1;
        SYNTH(l0.x, l1.x, l2.x, l3.x, h0.x, h1.x, h2.x, h3.x, o0.x, o1.x);
        SYNTH(l0.y, l1.y, l2.y, l3.y, h0.y, h1.y, h2.y, h3.y, o0.y, o1.y);
        ob[(size_t)(2 * bz) * plane2]     = o0;
        ob[(size_t)(2 * bz + 1) * plane2] = o1;
        l0 = l1; l1 = l2; l2 = l3;
        h0 = h1; h1 = h2; h2 = h3;
    }
}

extern "C" void kernel_launch(void* const* d_in, const int* in_sizes, int n_in,
                              void* d_out, int out_size) {
    const float *yl = nullptr, *yh0 = nullptr, *yh1 = nullptr;
    for (int i = 0; i < n_in; ++i) {
        if      (in_sizes[i] == 746496)   yl  = (const float*)d_in[i];  // (2,8,36,36,36)
        else if (in_sizes[i] == 32199552) yh0 = (const float*)d_in[i];  // (2,8,7,66,66,66)
        else if (in_sizes[i] == 5225472)  yh1 = (const float*)d_in[i];  // (2,8,7,36,36,36)
    }
    float* out = (float*)d_out;

    constexpr int SMEM1 = (2 * 36 * 68 + 4 * 8 * 36) * 4;   // 24,192 B
    constexpr int SMEM0 = (2 * 66 * 128 + 4 * 8 * 66) * 4;  // 76,032 B
    static bool attr_done = false;
    if (!attr_done) {
        cudaFuncSetAttribute(k_xy<66, true>,
                             cudaFuncAttributeMaxDynamicSharedMemorySize, SMEM0);
        attr_done = true;
    }

    // ---- Level 1: 36 -> 66 ----
    k_xy<36, false><<<dim3(36, 2, BC), 512, SMEM1>>>(yl, yh1);
    {
        int plane2 = 66 * 66 / 2;                  // 2178
        k_z<36, 2, true><<<dim3((plane2 + 255) / 256, 2, BC), 256>>>(nullptr, plane2);
    }

    // ---- Level 0: 66 -> 126 ----
    k_xy<66, true><<<dim3(66, 2, BC), 512, SMEM0>>>(nullptr, yh0);
    {
        int plane2 = 126 * 126 / 2;                // 7938
        k_z<66, 4, false><<<dim3((plane2 + 255) / 256, 4, BC), 256>>>(out, plane2);
    }
}

// round 11
// speedup vs baseline: 1.4966x; 1.4966x over previous
#include <cuda_runtime.h>

// 2-level 3D inverse db4 DWT.
// Kernel A: fused x+y synthesis per z-slice. Stage x: each thread computes TWO
//           adjacent pairs from 3 aligned float2 loads per band row (12 LDG.64
//           in flight, no barriers). Stage y: float2-vectorized.
// Kernel B: streaming z synthesis, float2 per thread, z-segmented (R7 config).
// out[i] = sum_d lo[(i>>1)+d]*CLO[i&1][d] + hi[(i>>1)+d]*CHI[i&1][d]

#define BC 16  // batch * channels

// db4: CLO[p][d] = g0[6+p-2d], CHI[p][d] = g1[6+p-2d]; literals -> FFMA-imm
#define CLO00  0.032883011666982945f
#define CLO01 -0.18703481171888114f
#define CLO02  0.6308807679295904f
#define CLO03  0.23037781330885523f
#define CLO10 -0.010597401784997278f
#define CLO11  0.030841381835986965f
#define CLO12 -0.02798376941698385f
#define CLO13  0.7148465705525415f
#define CHI00  0.7148465705525415f
#define CHI01 -0.02798376941698385f
#define CHI02  0.030841381835986965f
#define CHI03 -0.010597401784997278f
#define CHI10 -0.23037781330885523f
#define CHI11 -0.6308807679295904f
#define CHI12  0.18703481171888114f
#define CHI13 -0.032883011666982945f

#define SYNTH(l0,l1,l2,l3,h0,h1,h2,h3,o0,o1)                              \
    do {                                                                  \
        o0 = l0*CLO00 + l1*CLO01 + l2*CLO02 + l3*CLO03                    \
           + h0*CHI00 + h1*CHI01 + h2*CHI02 + h3*CHI03;                   \
        o1 = l0*CLO10 + l1*CLO11 + l2*CLO12 + l3*CLO13                    \
           + h0*CHI10 + h1*CHI11 + h2*CHI12 + h3*CHI13;                   \
    } while (0)

// Scratch: xy-fused output [2][BC][Nz][M][M] (sized for level 0), + level-1 LL
__device__ float g_U[2ull * BC * 66 * 126 * 126];
__device__ float g_LL[(size_t)BC * 66 * 66 * 66];

// ---------------- Kernel A: fused x+y synthesis for one z-slice ----------------
// grid = (Nz, 2 trees, BC), 512 threads. smem t: [2][N][MP], MP = M+2.
template<int N, bool LOW_LL>
__global__ __launch_bounds__(512)
void k_xy(const float* __restrict__ low_in, const float* __restrict__ highs) {
    constexpr int M  = 2 * N - 6;
    constexpr int MP = M + 2;      // even -> aligned float2/float4 smem rows
    constexpr int P  = N - 3;      // output pairs per axis (odd)
    constexpr int Q  = (P + 1) / 2;  // two-pair slots (last slot = 1 pair)
    extern __shared__ float t[];   // 2*N*MP floats

    const float* low = LOW_LL ? g_LL : low_in;
    const int z = blockIdx.x, i = blockIdx.y, b = blockIdx.z;
    const int tid = threadIdx.x;
    const size_t V  = (size_t)N * N * N;
    const size_t zb = (size_t)z * N * N;

    const int gl0 = 4 * i;
    const float* band0 = (gl0 == 0) ? (low + (size_t)b * V)
                                    : (highs + ((size_t)b * 7 + (gl0 - 1)) * V);
    const float* band1 = highs + ((size_t)b * 7 + gl0) * V;
    const float* band2 = highs + ((size_t)b * 7 + (4 * i + 1)) * V;
    const float* band3 = highs + ((size_t)b * 7 + (4 * i + 2)) * V;

    // ---- stage x: each thread owns pairs (2q, 2q+1) on rows y0, y0+16, ... ----
    {
        const int q  = tid & 31;       // 0..31
        const int y0 = tid >> 5;       // 0..15
        if (q < Q) {
            const bool full = (2 * q + 1 < P);     // last slot has 1 pair
            for (int y = y0; y < N; y += 16) {
                const size_t ro = zb + (size_t)y * N;
                const float2* a = (const float2*)(band0 + ro) + q;
                const float2* c = (const float2*)(band1 + ro) + q;
                const float2* e = (const float2*)(band2 + ro) + q;
                const float2* f = (const float2*)(band3 + ro) + q;
                if (full) {
                    // elements 2q..2q+5 per band: 3 aligned float2 loads each
                    float2 a01 = a[0], a23 = a[1], a45 = a[2];
                    float2 c01 = c[0], c23 = c[1], c45 = c[2];
                    float2 e01 = e[0], e23 = e[1], e45 = e[2];
                    float2 f01 = f[0], f23 = f[1], f45 = f[2];
                    float o0, o1, o2, o3, p0, p1, p2, p3;
                    SYNTH(a01.x, a01.y, a23.x, a23.y,
                          c01.x, c01.y, c23.x, c23.y, o0, o1);
                    SYNTH(a01.y, a23.x, a23.y, a45.x,
                          c01.y, c23.x, c23.y, c45.x, o2, o3);
                    SYNTH(e01.x, e01.y, e23.x, e23.y,
                          f01.x, f01.y, f23.x, f23.y, p0, p1);
                    SYNTH(e01.y, e23.x, e23.y, e45.x,
                          f01.y, f23.x, f23.y, f45.x, p2, p3);
                    *(float4*)&t[y * MP + 4 * q] = make_float4(o0, o1, o2, o3);
                    *(float4*)&t[(N + y) * MP + 4 * q] = make_float4(p0, p1, p2, p3);
                } else {
                    // single pair P-1: elements 2q..2q+3
                    float2 a01 = a[0], a23 = a[1];
                    float2 c01 = c[0], c23 = c[1];
                    float2 e01 = e[0], e23 = e[1];
                    float2 f01 = f[0], f23 = f[1];
                    float o0, o1, p0, p1;
                    SYNTH(a01.x, a01.y, a23.x, a23.y,
                          c01.x, c01.y, c23.x, c23.y, o0, o1);
                    SYNTH(e01.x, e01.y, e23.x, e23.y,
                          f01.x, f01.y, f23.x, f23.y, p0, p1);
                    *(float2*)&t[y * MP + 4 * q] = make_float2(o0, o1);
                    *(float2*)&t[(N + y) * MP + 4 * q] = make_float2(p0, p1);
                }
            }
        }
    }
    __syncthreads();

    // ---- stage y: float2 per thread along x; write g_U[i][b][z][*][*] ----
    {
        const int x2  = tid & 63;       // float2 index
        const int x   = 2 * x2;
        const int py0 = tid >> 6;       // 0..7
        if (x < M) {
            float* ub = g_U + ((((size_t)i * BC + b) * N + z) * M) * M + x;
            for (int py = py0; py < P; py += 8) {
                const float* r0 = &t[py * MP + x];        // sub-tree lo rows
                const float* r1 = &t[(N + py) * MP + x];  // sub-tree hi rows
                float2 l0 = *(const float2*)&r0[0];
                float2 l1 = *(const float2*)&r0[MP];
                float2 l2 = *(const float2*)&r0[2 * MP];
                float2 l3 = *(const float2*)&r0[3 * MP];
                float2 h0 = *(const float2*)&r1[0];
                float2 h1 = *(const float2*)&r1[MP];
                float2 h2 = *(const float2*)&r1[2 * MP];
                float2 h3 = *(const float2*)&r1[3 * MP];
                float2 o0, o1;
                SYNTH(l0.x, l1.x, l2.x, l3.x, h0.x, h1.x, h2.x, h3.x, o0.x, o1.x);
                SYNTH(l0.y, l1.y, l2.y, l3.y, h0.y, h1.y, h2.y, h3.y, o0.y, o1.y);
                float* d = ub + (size_t)(2 * py) * M;
                *(float2*)&d[0] = o0;
                *(float2*)&d[M] = o1;
            }
        }
    }
}

// ---------------- Kernel B: streaming z synthesis, float2, z-segmented ----------------
// (R7 configuration: measured 42.4us / 66.7% DRAM for level 0)
template<int NZ, int SEG, bool TO_LL>
__global__ __launch_bounds__(256)
void k_z(float* __restrict__ out_in, int plane2) {   // plane2 = plane/2
    const int pix = blockIdx.x * 256 + threadIdx.x;
    if (pix >= plane2) return;
    const int seg = blockIdx.y;
    const int b   = blockIdx.z;
    constexpr int MZ = 2 * NZ - 6;
    constexpr int P  = NZ - 3;
    constexpr int CH = (P + SEG - 1) / SEG;

    const int p0 = seg * CH;
    const int p1 = (p0 + CH < P) ? (p0 + CH) : P;

    float* out = TO_LL ? g_LL : out_in;
    const float2* lo = (const float2*)g_U + (size_t)b * NZ * plane2 + pix;
    const float2* hi = (const float2*)g_U + ((size_t)BC + b) * (size_t)NZ * plane2 + pix;
    float2* ob = (float2*)out + (size_t)b * MZ * plane2 + pix;

    float2 l0 = lo[(size_t)p0 * plane2];
    float2 l1 = lo[(size_t)(p0 + 1) * plane2];
    float2 l2 = lo[(size_t)(p0 + 2) * plane2];
    float2 h0 = hi[(size_t)p0 * plane2];
    float2 h1 = hi[(size_t)(p0 + 1) * plane2];
    float2 h2 = hi[(size_t)(p0 + 2) * plane2];
#pragma unroll 4
    for (int bz = p0; bz < p1; ++bz) {
        float2 l3 = lo[(size_t)(bz + 3) * plane2];
        float2 h3 = hi[(size_t)(bz + 3) * plane2];
        float2 o0, o1;
        SYNTH(l0.x, l1.x, l2.x, l3.x, h0.x, h1.x, h2.x, h3.x, o0.x, o1.x);
        SYNTH(l0.y, l1.y, l2.y, l3.y, h0.y, h1.y, h2.y, h3.y, o0.y, o1.y);
        ob[(size_t)(2 * bz) * plane2]     = o0;
        ob[(size_t)(2 * bz + 1) * plane2] = o1;
        l0 = l1; l1 = l2; l2 = l3;
        h0 = h1; h1 = h2; h2 = h3;
    }
}

extern "C" void kernel_launch(void* const* d_in, const int* in_sizes, int n_in,
                              void* d_out, int out_size) {
    const float *yl = nullptr, *yh0 = nullptr, *yh1 = nullptr;
    for (int i = 0; i < n_in; ++i) {
        if      (in_sizes[i] == 746496)   yl  = (const float*)d_in[i];  // (2,8,36,36,36)
        else if (in_sizes[i] == 32199552) yh0 = (const float*)d_in[i];  // (2,8,7,66,66,66)
        else if (in_sizes[i] == 5225472)  yh1 = (const float*)d_in[i];  // (2,8,7,36,36,36)
    }
    float* out = (float*)d_out;

    constexpr int SMEM1 = 2 * 36 * 68 * 4;   // 19,584 B
    constexpr int SMEM0 = 2 * 66 * 128 * 4;  // 67,584 B
    static bool attr_done = false;
    if (!attr_done) {
        cudaFuncSetAttribute(k_xy<66, true>,
                             cudaFuncAttributeMaxDynamicSharedMemorySize, SMEM0);
        attr_done = true;
    }

    // ---- Level 1: 36 -> 66 ----
    k_xy<36, false><<<dim3(36, 2, BC), 512, SMEM1>>>(yl, yh1);
    {
        int plane2 = 66 * 66 / 2;                  // 2178
        k_z<36, 2, true><<<dim3((plane2 + 255) / 256, 2, BC), 256>>>(nullptr, plane2);
    }

    // ---- Level 0: 66 -> 126 ----
    k_xy<66, true><<<dim3(66, 2, BC), 512, SMEM0>>>(nullptr, yh0);
    {
        int plane2 = 126 * 126 / 2;                // 7938
        k_z<66, 4, false><<<dim3((plane2 + 255) / 256, 4, BC), 256>>>(out, plane2);
    }
}

// round 12
// speedup vs baseline: 2.1920x; 1.4647x over previous
#include <cuda_runtime.h>
#include <cuda_fp16.h>

// 2-level 3D inverse db4 DWT.
// Kernel A: fused x+y synthesis per z-slice (R7 stage-x: 16 scalar LDGs
//           front-batched, no barriers in load loop; stage-y float2 from smem).
//           Writes the z-scratch g_U in FP16 (half2) to halve its traffic.
// Kernel B: streaming z synthesis, half2 loads -> float math -> float2 stores,
//           z-segmented (R7 config).
// out[i] = sum_d lo[(i>>1)+d]*CLO[i&1][d] + hi[(i>>1)+d]*CHI[i&1][d]

#define BC 16  // batch * channels

// db4: CLO[p][d] = g0[6+p-2d], CHI[p][d] = g1[6+p-2d]; literals -> FFMA-imm
#define CLO00  0.032883011666982945f
#define CLO01 -0.18703481171888114f
#define CLO02  0.6308807679295904f
#define CLO03  0.23037781330885523f
#define CLO10 -0.010597401784997278f
#define CLO11  0.030841381835986965f
#define CLO12 -0.02798376941698385f
#define CLO13  0.7148465705525415f
#define CHI00  0.7148465705525415f
#define CHI01 -0.02798376941698385f
#define CHI02  0.030841381835986965f
#define CHI03 -0.010597401784997278f
#define CHI10 -0.23037781330885523f
#define CHI11 -0.6308807679295904f
#define CHI12  0.18703481171888114f
#define CHI13 -0.032883011666982945f

#define SYNTH(l0,l1,l2,l3,h0,h1,h2,h3,o0,o1)                              \
    do {                                                                  \
        o0 = l0*CLO00 + l1*CLO01 + l2*CLO02 + l3*CLO03                    \
           + h0*CHI00 + h1*CHI01 + h2*CHI02 + h3*CHI03;                   \
        o1 = l0*CLO10 + l1*CLO11 + l2*CLO12 + l3*CLO13                    \
           + h0*CHI10 + h1*CHI11 + h2*CHI12 + h3*CHI13;                   \
    } while (0)

// Scratch: xy-fused output [2][BC][Nz][M][M] in FP16 (sized for level 0),
// plus level-1 LL result in FP32.
__device__ __half g_Uh[2ull * BC * 66 * 126 * 126];
__device__ float  g_LL[(size_t)BC * 66 * 66 * 66];

// ---------------- Kernel A: fused x+y synthesis for one z-slice ----------------
// grid = (Nz, 2 trees, BC), 512 threads. smem t: [2][N][MP], MP = M+2 (even ->
// aligned float2 rows; warp accesses row-contiguous, conflict-free).
template<int N, bool LOW_LL>
__global__ __launch_bounds__(512)
void k_xy(const float* __restrict__ low_in, const float* __restrict__ highs) {
    constexpr int M  = 2 * N - 6;
    constexpr int M2 = M / 2;
    constexpr int MP = M + 2;
    constexpr int P  = N - 3;      // output pairs per axis
    extern __shared__ float t[];   // 2*N*MP floats

    const float* low = LOW_LL ? g_LL : low_in;
    const int z = blockIdx.x, i = blockIdx.y, b = blockIdx.z;
    const int tid = threadIdx.x;
    const size_t V  = (size_t)N * N * N;
    const size_t zb = (size_t)z * N * N;

    // ---- stage x: pair-threads along rows; both sub-trees in one loop ----
    {
        const int px = tid & 63;
        const int y0 = tid >> 6;        // 0..7
        const int gl0 = 4 * i;
        const float* lo0 = (gl0 == 0) ? (low + (size_t)b * V)
                                      : (highs + ((size_t)b * 7 + (gl0 - 1)) * V);
        const float* hi0 = highs + ((size_t)b * 7 + gl0) * V;
        const float* lo1 = highs + ((size_t)b * 7 + (4 * i + 1)) * V;
        const float* hi1 = highs + ((size_t)b * 7 + (4 * i + 2)) * V;
        if (px < P) {
            for (int y = y0; y < N; y += 8) {
                const size_t ro = zb + (size_t)y * N + px;
                const float* a = lo0 + ro;  const float* c = hi0 + ro;
                const float* e = lo1 + ro;  const float* f = hi1 + ro;
                float a0 = a[0], a1 = a[1], a2 = a[2], a3 = a[3];
                float c0 = c[0], c1 = c[1], c2 = c[2], c3 = c[3];
                float e0 = e[0], e1 = e[1], e2 = e[2], e3 = e[3];
                float f0 = f[0], f1 = f[1], f2 = f[2], f3 = f[3];
                float o0, o1, p0, p1;
                SYNTH(a0, a1, a2, a3, c0, c1, c2, c3, o0, o1);
                SYNTH(e0, e1, e2, e3, f0, f1, f2, f3, p0, p1);
                *(float2*)&t[y * MP + 2 * px]       = make_float2(o0, o1);
                *(float2*)&t[(N + y) * MP + 2 * px] = make_float2(p0, p1);
            }
        }
    }
    __syncthreads();

    // ---- stage y: float2 per thread along x; write g_Uh (half2) ----
    {
        const int x2  = tid & 63;       // float2/half2 column index
        const int x   = 2 * x2;
        const int py0 = tid >> 6;       // 0..7
        if (x < M) {
            __half2* ub = (__half2*)g_Uh
                        + ((((size_t)i * BC + b) * N + z) * M) * M2 + x2;
            for (int py = py0; py < P; py += 8) {
                const float* r0 = &t[py * MP + x];        // sub-tree lo rows
                const float* r1 = &t[(N + py) * MP + x];  // sub-tree hi rows
                float2 l0 = *(const float2*)&r0[0];
                float2 l1 = *(const float2*)&r0[MP];
                float2 l2 = *(const float2*)&r0[2 * MP];
                float2 l3 = *(const float2*)&r0[3 * MP];
                float2 h0 = *(const float2*)&r1[0];
                float2 h1 = *(const float2*)&r1[MP];
                float2 h2 = *(const float2*)&r1[2 * MP];
                float2 h3 = *(const float2*)&r1[3 * MP];
                float2 o0, o1;
                SYNTH(l0.x, l1.x, l2.x, l3.x, h0.x, h1.x, h2.x, h3.x, o0.x, o1.x);
                SYNTH(l0.y, l1.y, l2.y, l3.y, h0.y, h1.y, h2.y, h3.y, o0.y, o1.y);
                ub[(size_t)(2 * py) * M2]     = __float22half2_rn(o0);
                ub[(size_t)(2 * py + 1) * M2] = __float22half2_rn(o1);
            }
        }
    }
}

// ---------------- Kernel B: streaming z synthesis, half2 in / float2 out ----------------
// g_Uh[0][b] = lo tree, g_Uh[1][b] = hi tree, each [NZ][plane] halves.
// grid.y = segment, grid.z = b; segment handles pairs [p0, p1).
template<int NZ, int SEG, bool TO_LL>
__global__ __launch_bounds__(256)
void k_z(float* __restrict__ out_in, int plane2) {   // plane2 = plane/2
    const int pix = blockIdx.x * 256 + threadIdx.x;
    if (pix >= plane2) return;
    const int seg = blockIdx.y;
    const int b   = blockIdx.z;
    constexpr int MZ = 2 * NZ - 6;
    constexpr int P  = NZ - 3;
    constexpr int CH = (P + SEG - 1) / SEG;

    const int p0 = seg * CH;
    const int p1 = (p0 + CH < P) ? (p0 + CH) : P;

    float* out = TO_LL ? g_LL : out_in;
    const __half2* lo = (const __half2*)g_Uh + (size_t)b * NZ * plane2 + pix;
    const __half2* hi = (const __half2*)g_Uh + ((size_t)BC + b) * (size_t)NZ * plane2 + pix;
    float2* ob = (float2*)out + (size_t)b * MZ * plane2 + pix;

    float2 l0 = __half22float2(lo[(size_t)p0 * plane2]);
    float2 l1 = __half22float2(lo[(size_t)(p0 + 1) * plane2]);
    float2 l2 = __half22float2(lo[(size_t)(p0 + 2) * plane2]);
    float2 h0 = __half22float2(hi[(size_t)p0 * plane2]);
    float2 h1 = __half22float2(hi[(size_t)(p0 + 1) * plane2]);
    float2 h2 = __half22float2(hi[(size_t)(p0 + 2) * plane2]);
#pragma unroll 4
    for (int bz = p0; bz < p1; ++bz) {
        float2 l3 = __half22float2(lo[(size_t)(bz + 3) * plane2]);
        float2 h3 = __half22float2(hi[(size_t)(bz + 3) * plane2]);
        float2 o0, o1;
        SYNTH(l0.x, l1.x, l2.x, l3.x, h0.x, h1.x, h2.x, h3.x, o0.x, o1.x);
        SYNTH(l0.y, l1.y, l2.y, l3.y, h0.y, h1.y, h2.y, h3.y, o0.y, o1.y);
        ob[(size_t)(2 * bz) * plane2]     = o0;
        ob[(size_t)(2 * bz + 1) * plane2] = o1;
        l0 = l1; l1 = l2; l2 = l3;
        h0 = h1; h1 = h2; h2 = h3;
    }
}

extern "C" void kernel_launch(void* const* d_in, const int* in_sizes, int n_in,
                              void* d_out, int out_size) {
    const float *yl = nullptr, *yh0 = nullptr, *yh1 = nullptr;
    for (int i = 0; i < n_in; ++i) {
        if      (in_sizes[i] == 746496)   yl  = (const float*)d_in[i];  // (2,8,36,36,36)
        else if (in_sizes[i] == 32199552) yh0 = (const float*)d_in[i];  // (2,8,7,66,66,66)
        else if (in_sizes[i] == 5225472)  yh1 = (const float*)d_in[i];  // (2,8,7,36,36,36)
    }
    float* out = (float*)d_out;

    constexpr int SMEM1 = 2 * 36 * 68 * 4;   // 19,584 B
    constexpr int SMEM0 = 2 * 66 * 128 * 4;  // 67,584 B
    static bool attr_done = false;
    if (!attr_done) {
        cudaFuncSetAttribute(k_xy<66, true>,
                             cudaFuncAttributeMaxDynamicSharedMemorySize, SMEM0);
        attr_done = true;
    }

    // ---- Level 1: 36 -> 66 ----
    k_xy<36, false><<<dim3(36, 2, BC), 512, SMEM1>>>(yl, yh1);
    {
        int plane2 = 66 * 66 / 2;                  // 2178
        k_z<36, 2, true><<<dim3((plane2 + 255) / 256, 2, BC), 256>>>(nullptr, plane2);
    }

    // ---- Level 0: 66 -> 126 ----
    k_xy<66, true><<<dim3(66, 2, BC), 512, SMEM0>>>(nullptr, yh0);
    {
        int plane2 = 126 * 126 / 2;                // 7938
        k_z<66, 4, false><<<dim3((plane2 + 255) / 256, 4, BC), 256>>>(out, plane2);
    }
}

// round 13
// speedup vs baseline: 2.2610x; 1.0315x over previous
#include <cuda_runtime.h>
#include <cuda_fp16.h>

// 2-level 3D inverse db4 DWT.
// Kernel A: fused x+y synthesis per z-slice. Stage x: 16 front-batched scalar
//           LDGs per pair-thread (proven coalesced/MLP-rich pattern). Stage y:
//           rolling 4-row window per thread (8 consecutive pairs, 22 LDS.64
//           instead of 64). Writes z-scratch in FP16 (half2).
// Kernel B: streaming z synthesis, half2 in / float2 out, z-segmented.
// out[i] = sum_d lo[(i>>1)+d]*CLO[i&1][d] + hi[(i>>1)+d]*CHI[i&1][d]

#define BC 16  // batch * channels

// db4: CLO[p][d] = g0[6+p-2d], CHI[p][d] = g1[6+p-2d]; literals -> FFMA-imm
#define CLO00  0.032883011666982945f
#define CLO01 -0.18703481171888114f
#define CLO02  0.6308807679295904f
#define CLO03  0.23037781330885523f
#define CLO10 -0.010597401784997278f
#define CLO11  0.030841381835986965f
#define CLO12 -0.02798376941698385f
#define CLO13  0.7148465705525415f
#define CHI00  0.7148465705525415f
#define CHI01 -0.02798376941698385f
#define CHI02  0.030841381835986965f
#define CHI03 -0.010597401784997278f
#define CHI10 -0.23037781330885523f
#define CHI11 -0.6308807679295904f
#define CHI12  0.18703481171888114f
#define CHI13 -0.032883011666982945f

#define SYNTH(l0,l1,l2,l3,h0,h1,h2,h3,o0,o1)                              \
    do {                                                                  \
        o0 = l0*CLO00 + l1*CLO01 + l2*CLO02 + l3*CLO03                    \
           + h0*CHI00 + h1*CHI01 + h2*CHI02 + h3*CHI03;                   \
        o1 = l0*CLO10 + l1*CLO11 + l2*CLO12 + l3*CLO13                    \
           + h0*CHI10 + h1*CHI11 + h2*CHI12 + h3*CHI13;                   \
    } while (0)

// Scratch: xy-fused output [2][BC][Nz][M][M] in FP16 (sized for level 0),
// plus level-1 LL result in FP32.
__device__ __half g_Uh[2ull * BC * 66 * 126 * 126];
__device__ float  g_LL[(size_t)BC * 66 * 66 * 66];

// ---------------- Kernel A: fused x+y synthesis for one z-slice ----------------
// grid = (Nz, 2 trees, BC), 512 threads. smem t: [2][N][MP], MP = M+2.
template<int N, bool LOW_LL>
__global__ __launch_bounds__(512)
void k_xy(const float* __restrict__ low_in, const float* __restrict__ highs) {
    constexpr int M  = 2 * N - 6;
    constexpr int M2 = M / 2;
    constexpr int MP = M + 2;
    constexpr int P  = N - 3;      // output pairs per axis
    extern __shared__ float t[];   // 2*N*MP floats

    const float* low = LOW_LL ? g_LL : low_in;
    const int z = blockIdx.x, i = blockIdx.y, b = blockIdx.z;
    const int tid = threadIdx.x;
    const size_t V  = (size_t)N * N * N;
    const size_t zb = (size_t)z * N * N;

    // ---- stage x: pair-threads along rows; both sub-trees in one loop ----
    {
        const int px = tid & 63;
        const int y0 = tid >> 6;        // 0..7
        const int gl0 = 4 * i;
        const float* lo0 = (gl0 == 0) ? (low + (size_t)b * V)
                                      : (highs + ((size_t)b * 7 + (gl0 - 1)) * V);
        const float* hi0 = highs + ((size_t)b * 7 + gl0) * V;
        const float* lo1 = highs + ((size_t)b * 7 + (4 * i + 1)) * V;
        const float* hi1 = highs + ((size_t)b * 7 + (4 * i + 2)) * V;
        if (px < P) {
            for (int y = y0; y < N; y += 8) {
                const size_t ro = zb + (size_t)y * N + px;
                const float* a = lo0 + ro;  const float* c = hi0 + ro;
                const float* e = lo1 + ro;  const float* f = hi1 + ro;
                float a0 = a[0], a1 = a[1], a2 = a[2], a3 = a[3];
                float c0 = c[0], c1 = c[1], c2 = c[2], c3 = c[3];
                float e0 = e[0], e1 = e[1], e2 = e[2], e3 = e[3];
                float f0 = f[0], f1 = f[1], f2 = f[2], f3 = f[3];
                float o0, o1, p0, p1;
                SYNTH(a0, a1, a2, a3, c0, c1, c2, c3, o0, o1);
                SYNTH(e0, e1, e2, e3, f0, f1, f2, f3, p0, p1);
                *(float2*)&t[y * MP + 2 * px]       = make_float2(o0, o1);
                *(float2*)&t[(N + y) * MP + 2 * px] = make_float2(p0, p1);
            }
        }
    }
    __syncthreads();

    // ---- stage y: rolling 4-row window; 8 consecutive pairs per thread ----
    {
        const int x2 = tid & 63;        // half2/float2 column index
        const int x  = 2 * x2;
        const int st = tid >> 6;        // slot 0..7
        constexpr int CHY = (P + 7) / 8;
        const int py0 = st * CHY;
        const int py1 = (py0 + CHY < P) ? (py0 + CHY) : P;
        if (x < M && py0 < P) {
            __half2* ub = (__half2*)g_Uh
                        + ((((size_t)i * BC + b) * N + z) * M) * M2 + x2;
            float2 l0 = *(const float2*)&t[(py0    ) * MP + x];
            float2 l1 = *(const float2*)&t[(py0 + 1) * MP + x];
            float2 l2 = *(const float2*)&t[(py0 + 2) * MP + x];
            float2 h0 = *(const float2*)&t[(N + py0    ) * MP + x];
            float2 h1 = *(const float2*)&t[(N + py0 + 1) * MP + x];
            float2 h2 = *(const float2*)&t[(N + py0 + 2) * MP + x];
#pragma unroll 4
            for (int py = py0; py < py1; ++py) {
                float2 l3 = *(const float2*)&t[(py + 3) * MP + x];
                float2 h3 = *(const float2*)&t[(N + py + 3) * MP + x];
                float2 o0, o1;
                SYNTH(l0.x, l1.x, l2.x, l3.x, h0.x, h1.x, h2.x, h3.x, o0.x, o1.x);
                SYNTH(l0.y, l1.y, l2.y, l3.y, h0.y, h1.y, h2.y, h3.y, o0.y, o1.y);
                ub[(size_t)(2 * py) * M2]     = __float22half2_rn(o0);
                ub[(size_t)(2 * py + 1) * M2] = __float22half2_rn(o1);
                l0 = l1; l1 = l2; l2 = l3;
                h0 = h1; h1 = h2; h2 = h3;
            }
        }
    }
}

// ---------------- Kernel B: streaming z synthesis, half2 in / float2 out ----------------
// g_Uh[0][b] = lo tree, g_Uh[1][b] = hi tree, each [NZ][plane] halves.
// grid.y = segment, grid.z = b; segment handles pairs [p0, p1).
template<int NZ, int SEG, bool TO_LL>
__global__ __launch_bounds__(256)
void k_z(float* __restrict__ out_in, int plane2) {   // plane2 = plane/2
    const int pix = blockIdx.x * 256 + threadIdx.x;
    if (pix >= plane2) return;
    const int seg = blockIdx.y;
    const int b   = blockIdx.z;
    constexpr int MZ = 2 * NZ - 6;
    constexpr int P  = NZ - 3;
    constexpr int CH = (P + SEG - 1) / SEG;

    const int p0 = seg * CH;
    const int p1 = (p0 + CH < P) ? (p0 + CH) : P;

    float* out = TO_LL ? g_LL : out_in;
    const __half2* lo = (const __half2*)g_Uh + (size_t)b * NZ * plane2 + pix;
    const __half2* hi = (const __half2*)g_Uh + ((size_t)BC + b) * (size_t)NZ * plane2 + pix;
    float2* ob = (float2*)out + (size_t)b * MZ * plane2 + pix;

    float2 l0 = __half22float2(lo[(size_t)p0 * plane2]);
    float2 l1 = __half22float2(lo[(size_t)(p0 + 1) * plane2]);
    float2 l2 = __half22float2(lo[(size_t)(p0 + 2) * plane2]);
    float2 h0 = __half22float2(hi[(size_t)p0 * plane2]);
    float2 h1 = __half22float2(hi[(size_t)(p0 + 1) * plane2]);
    float2 h2 = __half22float2(hi[(size_t)(p0 + 2) * plane2]);
#pragma unroll 4
    for (int bz = p0; bz < p1; ++bz) {
        float2 l3 = __half22float2(lo[(size_t)(bz + 3) * plane2]);
        float2 h3 = __half22float2(hi[(size_t)(bz + 3) * plane2]);
        float2 o0, o1;
        SYNTH(l0.x, l1.x, l2.x, l3.x, h0.x, h1.x, h2.x, h3.x, o0.x, o1.x);
        SYNTH(l0.y, l1.y, l2.y, l3.y, h0.y, h1.y, h2.y, h3.y, o0.y, o1.y);
        ob[(size_t)(2 * bz) * plane2]     = o0;
        ob[(size_t)(2 * bz + 1) * plane2] = o1;
        l0 = l1; l1 = l2; l2 = l3;
        h0 = h1; h1 = h2; h2 = h3;
    }
}

extern "C" void kernel_launch(void* const* d_in, const int* in_sizes, int n_in,
                              void* d_out, int out_size) {
    const float *yl = nullptr, *yh0 = nullptr, *yh1 = nullptr;
    for (int i = 0; i < n_in; ++i) {
        if      (in_sizes[i] == 746496)   yl  = (const float*)d_in[i];  // (2,8,36,36,36)
        else if (in_sizes[i] == 32199552) yh0 = (const float*)d_in[i];  // (2,8,7,66,66,66)
        else if (in_sizes[i] == 5225472)  yh1 = (const float*)d_in[i];  // (2,8,7,36,36,36)
    }
    float* out = (float*)d_out;

    constexpr int SMEM1 = 2 * 36 * 68 * 4;   // 19,584 B
    constexpr int SMEM0 = 2 * 66 * 128 * 4;  // 67,584 B
    static bool attr_done = false;
    if (!attr_done) {
        cudaFuncSetAttribute(k_xy<66, true>,
                             cudaFuncAttributeMaxDynamicSharedMemorySize, SMEM0);
        attr_done = true;
    }

    // ---- Level 1: 36 -> 66 ----
    k_xy<36, false><<<dim3(36, 2, BC), 512, SMEM1>>>(yl, yh1);
    {
        int plane2 = 66 * 66 / 2;                  // 2178
        k_z<36, 2, true><<<dim3((plane2 + 255) / 256, 2, BC), 256>>>(nullptr, plane2);
    }

    // ---- Level 0: 66 -> 126 ----
    k_xy<66, true><<<dim3(66, 2, BC), 512, SMEM0>>>(nullptr, yh0);
    {
        int plane2 = 126 * 126 / 2;                // 7938
        k_z<66, 4, false><<<dim3((plane2 + 255) / 256, 4, BC), 256>>>(out, plane2);
    }
}

// round 15
// speedup vs baseline: 2.3273x; 1.0293x over previous
#include <cuda_runtime.h>
#include <cuda_fp16.h>

// 2-level 3D inverse db4 DWT.
// Kernel A: fused x+y synthesis per z-slice.
//   Stage x (N>=64): two pairs per thread from 3 aligned float2 loads per band
//     row, sub-trees processed sequentially (low register pressure), float4 STS.
//   Stage x (N<64):  proven scalar pair-per-thread path.
//   Stage y: rolling 4-row window per thread, half2 stores to fp16 z-scratch.
// Kernel B: streaming z synthesis, half2 in / float2 out, z-segmented.
// out[i] = sum_d lo[(i>>1)+d]*CLO[i&1][d] + hi[(i>>1)+d]*CHI[i&1][d]

#define BC 16  // batch * channels

// db4: CLO[p][d] = g0[6+p-2d], CHI[p][d] = g1[6+p-2d]; literals -> FFMA-imm
#define CLO00  0.032883011666982945f
#define CLO01 -0.18703481171888114f
#define CLO02  0.6308807679295904f
#define CLO03  0.23037781330885523f
#define CLO10 -0.010597401784997278f
#define CLO11  0.030841381835986965f
#define CLO12 -0.02798376941698385f
#define CLO13  0.7148465705525415f
#define CHI00  0.7148465705525415f
#define CHI01 -0.02798376941698385f
#define CHI02  0.030841381835986965f
#define CHI03 -0.010597401784997278f
#define CHI10 -0.23037781330885523f
#define CHI11 -0.6308807679295904f
#define CHI12  0.18703481171888114f
#define CHI13 -0.032883011666982945f

#define SYNTH(l0,l1,l2,l3,h0,h1,h2,h3,o0,o1)                              \
    do {                                                                  \
        o0 = l0*CLO00 + l1*CLO01 + l2*CLO02 + l3*CLO03                    \
           + h0*CHI00 + h1*CHI01 + h2*CHI02 + h3*CHI03;                   \
        o1 = l0*CLO10 + l1*CLO11 + l2*CLO12 + l3*CLO13                    \
           + h0*CHI10 + h1*CHI11 + h2*CHI12 + h3*CHI13;                   \
    } while (0)

// Scratch: xy-fused output [2][BC][Nz][M][M] in FP16 (sized for level 0),
// plus level-1 LL result in FP32.
__device__ __half g_Uh[2ull * BC * 66 * 126 * 126];
__device__ float  g_LL[(size_t)BC * 66 * 66 * 66];

// ---------------- Kernel A: fused x+y synthesis for one z-slice ----------------
// grid = (Nz, 2 trees, BC), 512 threads. smem t: [2][N][MP], MP = M+2.
template<int N, bool LOW_LL>
__global__ __launch_bounds__(512, 3)
void k_xy(const float* __restrict__ low_in, const float* __restrict__ highs) {
    constexpr int M  = 2 * N - 6;
    constexpr int M2 = M / 2;
    constexpr int MP = M + 2;
    constexpr int P  = N - 3;      // output pairs per axis
    extern __shared__ float t[];   // 2*N*MP floats

    const float* low = LOW_LL ? g_LL : low_in;
    const int z = blockIdx.x, i = blockIdx.y, b = blockIdx.z;
    const int tid = threadIdx.x;
    const size_t V  = (size_t)N * N * N;
    const size_t zb = (size_t)z * N * N;

    const int gl0 = 4 * i;
    const float* band0 = (gl0 == 0) ? (low + (size_t)b * V)
                                    : (highs + ((size_t)b * 7 + (gl0 - 1)) * V);
    const float* band1 = highs + ((size_t)b * 7 + gl0) * V;
    const float* band2 = highs + ((size_t)b * 7 + (4 * i + 1)) * V;
    const float* band3 = highs + ((size_t)b * 7 + (4 * i + 2)) * V;

    if constexpr (N >= 64) {
        // ---- stage x: two pairs per thread, sequential sub-trees ----
        constexpr int Q = (P + 1) / 2;     // 32 slots (last = single pair)
        const int q  = tid & 31;           // 0..31
        const int y0 = tid >> 5;           // 0..15
        if (q < Q) {
            const bool full = (2 * q + 1 < P);
            for (int y = y0; y < N; y += 16) {
                const size_t ro = zb + (size_t)y * N;
                // sub-tree 0 (bands 0,1)
                {
                    const float2* A = (const float2*)(band0 + ro) + q;
                    const float2* C = (const float2*)(band1 + ro) + q;
                    if (full) {
                        float2 a0 = A[0], a1 = A[1], a2 = A[2];
                        float2 c0 = C[0], c1 = C[1], c2 = C[2];
                        float o0, o1, o2, o3;
                        SYNTH(a0.x, a0.y, a1.x, a1.y,
                              c0.x, c0.y, c1.x, c1.y, o0, o1);
                        SYNTH(a0.y, a1.x, a1.y, a2.x,
                              c0.y, c1.x, c1.y, c2.x, o2, o3);
                        *(float4*)&t[y * MP + 4 * q] = make_float4(o0, o1, o2, o3);
                    } else {
                        float2 a0 = A[0], a1 = A[1];
                        float2 c0 = C[0], c1 = C[1];
                        float o0, o1;
                        SYNTH(a0.x, a0.y, a1.x, a1.y,
                              c0.x, c0.y, c1.x, c1.y, o0, o1);
                        *(float2*)&t[y * MP + 4 * q] = make_float2(o0, o1);
                    }
                }
                // sub-tree 1 (bands 2,3)
                {
                    const float2* E = (const float2*)(band2 + ro) + q;
                    const float2* F = (const float2*)(band3 + ro) + q;
                    if (full) {
                        float2 e0 = E[0], e1 = E[1], e2 = E[2];
                        float2 f0 = F[0], f1 = F[1], f2 = F[2];
                        float p0, p1, p2, p3;
                        SYNTH(e0.x, e0.y, e1.x, e1.y,
                              f0.x, f0.y, f1.x, f1.y, p0, p1);
                        SYNTH(e0.y, e1.x, e1.y, e2.x,
                              f0.y, f1.x, f1.y, f2.x, p2, p3);
                        *(float4*)&t[(N + y) * MP + 4 * q] = make_float4(p0, p1, p2, p3);
                    } else {
                        float2 e0 = E[0], e1 = E[1];
                        float2 f0 = F[0], f1 = F[1];
                        float p0, p1;
                        SYNTH(e0.x, e0.y, e1.x, e1.y,
                              f0.x, f0.y, f1.x, f1.y, p0, p1);
                        *(float2*)&t[(N + y) * MP + 4 * q] = make_float2(p0, p1);
                    }
                }
            }
        }
    } else {
        // ---- stage x: scalar pair-per-thread (proven R12 path) ----
        const int px = tid & 63;
        const int y0 = tid >> 6;        // 0..7
        if (px < P) {
            for (int y = y0; y < N; y += 8) {
                const size_t ro = zb + (size_t)y * N + px;
                const float* a = band0 + ro;  const float* c = band1 + ro;
                const float* e = band2 + ro;  const float* f = band3 + ro;
                float a0 = a[0], a1 = a[1], a2 = a[2], a3 = a[3];
                float c0 = c[0], c1 = c[1], c2 = c[2], c3 = c[3];
                float e0 = e[0], e1 = e[1], e2 = e[2], e3 = e[3];
                float f0 = f[0], f1 = f[1], f2 = f[2], f3 = f[3];
                float o0, o1, p0, p1;
                SYNTH(a0, a1, a2, a3, c0, c1, c2, c3, o0, o1);
                SYNTH(e0, e1, e2, e3, f0, f1, f2, f3, p0, p1);
                *(float2*)&t[y * MP + 2 * px]       = make_float2(o0, o1);
                *(float2*)&t[(N + y) * MP + 2 * px] = make_float2(p0, p1);
            }
        }
    }
    __syncthreads();

    // ---- stage y: rolling 4-row window; block of consecutive pairs ----
    {
        const int x2 = tid & 63;        // half2/float2 column index
        const int x  = 2 * x2;
        const int st = tid >> 6;        // slot 0..7
        constexpr int CHY = (P + 7) / 8;
        const int py0 = st * CHY;
        const int py1 = (py0 + CHY < P) ? (py0 + CHY) : P;
        if (x < M && py0 < P) {
            __half2* ub = (__half2*)g_Uh
                        + ((((size_t)i * BC + b) * N + z) * M) * M2 + x2;
            float2 l0 = *(const float2*)&t[(py0    ) * MP + x];
            float2 l1 = *(const float2*)&t[(py0 + 1) * MP + x];
            float2 l2 = *(const float2*)&t[(py0 + 2) * MP + x];
            float2 h0 = *(const float2*)&t[(N + py0    ) * MP + x];
            float2 h1 = *(const float2*)&t[(N + py0 + 1) * MP + x];
            float2 h2 = *(const float2*)&t[(N + py0 + 2) * MP + x];
#pragma unroll 4
            for (int py = py0; py < py1; ++py) {
                float2 l3 = *(const float2*)&t[(py + 3) * MP + x];
                float2 h3 = *(const float2*)&t[(N + py + 3) * MP + x];
                float2 o0, o1;
                SYNTH(l0.x, l1.x, l2.x, l3.x, h0.x, h1.x, h2.x, h3.x, o0.x, o1.x);
                SYNTH(l0.y, l1.y, l2.y, l3.y, h0.y, h1.y, h2.y, h3.y, o0.y, o1.y);
                ub[(size_t)(2 * py) * M2]     = __float22half2_rn(o0);
                ub[(size_t)(2 * py + 1) * M2] = __float22half2_rn(o1);
                l0 = l1; l1 = l2; l2 = l3;
                h0 = h1; h1 = h2; h2 = h3;
            }
        }
    }
}

// ---------------- Kernel B: streaming z synthesis, half2 in / float2 out ----------------
// g_Uh[0][b] = lo tree, g_Uh[1][b] = hi tree, each [NZ][plane] halves.
// grid.y = segment, grid.z = b; segment handles pairs [p0, p1).
template<int NZ, int SEG, bool TO_LL>
__global__ __launch_bounds__(256)
void k_z(float* __restrict__ out_in, int plane2) {   // plane2 = plane/2
    const int pix = blockIdx.x * 256 + threadIdx.x;
    if (pix >= plane2) return;
    const int seg = blockIdx.y;
    const int b   = blockIdx.z;
    constexpr int MZ = 2 * NZ - 6;
    constexpr int P  = NZ - 3;
    constexpr int CH = (P + SEG - 1) / SEG;

    const int p0 = seg * CH;
    const int p1 = (p0 + CH < P) ? (p0 + CH) : P;

    float* out = TO_LL ? g_LL : out_in;
    const __half2* lo = (const __half2*)g_Uh + (size_t)b * NZ * plane2 + pix;
    const __half2* hi = (const __half2*)g_Uh + ((size_t)BC + b) * (size_t)NZ * plane2 + pix;
    float2* ob = (float2*)out + (size_t)b * MZ * plane2 + pix;

    float2 l0 = __half22float2(lo[(size_t)p0 * plane2]);
    float2 l1 = __half22float2(lo[(size_t)(p0 + 1) * plane2]);
    float2 l2 = __half22float2(lo[(size_t)(p0 + 2) * plane2]);
    float2 h0 = __half22float2(hi[(size_t)p0 * plane2]);
    float2 h1 = __half22float2(hi[(size_t)(p0 + 1) * plane2]);
    float2 h2 = __half22float2(hi[(size_t)(p0 + 2) * plane2]);
#pragma unroll 4
    for (int bz = p0; bz < p1; ++bz) {
        float2 l3 = __half22float2(lo[(size_t)(bz + 3) * plane2]);
        float2 h3 = __half22float2(hi[(size_t)(bz + 3) * plane2]);
        float2 o0, o1;
        SYNTH(l0.x, l1.x, l2.x, l3.x, h0.x, h1.x, h2.x, h3.x, o0.x, o1.x);
        SYNTH(l0.y, l1.y, l2.y, l3.y, h0.y, h1.y, h2.y, h3.y, o0.y, o1.y);
        ob[(size_t)(2 * bz) * plane2]     = o0;
        ob[(size_t)(2 * bz + 1) * plane2] = o1;
        l0 = l1; l1 = l2; l2 = l3;
        h0 = h1; h1 = h2; h2 = h3;
    }
}

extern "C" void kernel_launch(void* const* d_in, const int* in_sizes, int n_in,
                              void* d_out, int out_size) {
    const float *yl = nullptr, *yh0 = nullptr, *yh1 = nullptr;
    for (int i = 0; i < n_in; ++i) {
        if      (in_sizes[i] == 746496)   yl  = (const float*)d_in[i];  // (2,8,36,36,36)
        else if (in_sizes[i] == 32199552) yh0 = (const float*)d_in[i];  // (2,8,7,66,66,66)
        else if (in_sizes[i] == 5225472)  yh1 = (const float*)d_in[i];  // (2,8,7,36,36,36)
    }
    float* out = (float*)d_out;

    constexpr int SMEM1 = 2 * 36 * 68 * 4;   // 19,584 B
    constexpr int SMEM0 = 2 * 66 * 128 * 4;  // 67,584 B
    static bool attr_done = false;
    if (!attr_done) {
        cudaFuncSetAttribute(k_xy<66, true>,
                             cudaFuncAttributeMaxDynamicSharedMemorySize, SMEM0);
        attr_done = true;
    }

    // ---- Level 1: 36 -> 66 ----
    k_xy<36, false><<<dim3(36, 2, BC), 512, SMEM1>>>(yl, yh1);
    {
        int plane2 = 66 * 66 / 2;                  // 2178
        k_z<36, 2, true><<<dim3((plane2 + 255) / 256, 2, BC), 256>>>(nullptr, plane2);
    }

    // ---- Level 0: 66 -> 126 ----
    k_xy<66, true><<<dim3(66, 2, BC), 512, SMEM0>>>(nullptr, yh0);
    {
        int plane2 = 126 * 126 / 2;                // 7938
        k_z<66, 4, false><<<dim3((plane2 + 255) / 256, 4, BC), 256>>>(out, plane2);
    }
}